// round 7
// baseline (speedup 1.0000x reference)
#include <cuda_runtime.h>
#include <cuda_bf16.h>
#include <math.h>
#include <stdint.h>

#define T_LEN   65536
#define HID     256
#define K0PAD   96          // layer-0 K (real 72) padded to 3x32
#define IN_RAW  72
#define NOUT    1024        // 4*HID interleaved weight rows
#define NH      (T_LEN / 128)   // 512 half-chunks of 128 timesteps

// ======================= scratch =======================
static __device__ __nv_bfloat16 g_A0[(size_t)T_LEN * K0PAD];
static __device__ __nv_bfloat16 g_A1[(size_t)T_LEN * HID];
static __device__ __nv_bfloat16 g_W0[NOUT * K0PAD];
static __device__ __nv_bfloat16 g_W1[NOUT * HID];
static __device__ float g_abar[(size_t)T_LEN * HID];
static __device__ float g_bx  [(size_t)T_LEN * HID];
static __device__ __nv_bfloat16 g_c[(size_t)T_LEN * HID];
static __device__ float g_Ph  [NH * HID];
static __device__ float g_Sh  [NH * HID];
static __device__ float g_H0h [NH * HID];
static __device__ float g_negA[2 * HID];

__device__ __forceinline__ uint32_t smem_u32(const void* p) {
    uint32_t a;
    asm("{ .reg .u64 t; cvta.to.shared.u64 t, %1; cvt.u32.u64 %0, t; }" : "=r"(a) : "l"(p));
    return a;
}

#define CP16(so, gp) \
    asm volatile("cp.async.cg.shared.global [%0], [%1], 16;" :: "r"(so), "l"(gp) : "memory")
#define CP_COMMIT() asm volatile("cp.async.commit_group;" ::: "memory")
#define CP_WAIT(n)  asm volatile("cp.async.wait_group %0;" :: "n"(n) : "memory")

#define LDSM4(r, addr) \
    asm volatile("ldmatrix.sync.aligned.m8n8.x4.shared.b16 {%0,%1,%2,%3}, [%4];" \
        : "=r"((r)[0]), "=r"((r)[1]), "=r"((r)[2]), "=r"((r)[3]) : "r"(addr))

// non-volatile: lets ptxas schedule/interleave MMAs
#define MMA(d, a, b) \
    asm("mma.sync.aligned.m16n8k16.row.col.f32.bf16.bf16.f32 " \
        "{%0,%1,%2,%3}, {%4,%5,%6,%7}, {%8,%9}, {%0,%1,%2,%3};" \
        : "+f"((d)[0]), "+f"((d)[1]), "+f"((d)[2]), "+f"((d)[3]) \
        : "r"((a)[0]), "r"((a)[1]), "r"((a)[2]), "r"((a)[3]), \
          "r"((b)[0]), "r"((b)[1]))

// ======================= prep =======================
__global__ void prep_w0_kernel(const float* __restrict__ Win, const float* __restrict__ WB,
                               const float* __restrict__ WC, const float* __restrict__ Wd) {
    int idx = blockIdx.x * 256 + threadIdx.x;          // NOUT*K0PAD
    int r = idx / K0PAD, k = idx % K0PAD;
    int h = r >> 2, j = r & 3;
    float v = 0.f;
    if (k < IN_RAW) {
        const float* s = (j == 0) ? Win : (j == 1) ? WB : (j == 2) ? WC : Wd;
        v = s[h * IN_RAW + k];
    }
    g_W0[idx] = __float2bfloat16(v);
}

__global__ void prep_w1_kernel(const float* __restrict__ Win, const float* __restrict__ WB,
                               const float* __restrict__ WC, const float* __restrict__ Wd) {
    int idx = blockIdx.x * 256 + threadIdx.x;          // NOUT*HID
    int r = idx / HID, k = idx % HID;
    int h = r >> 2, j = r & 3;
    const float* s = (j == 0) ? Win : (j == 1) ? WB : (j == 2) ? WC : Wd;
    g_W1[idx] = __float2bfloat16(s[h * HID + k]);
}

__global__ void prep_a_kernel(const float* __restrict__ A0, const float* __restrict__ A1) {
    int h = threadIdx.x;
    g_negA[h] = -expf(A0[h]);
    g_negA[HID + h] = -expf(A1[h]);
}

// 2D vectorized: block (24, 8); thread = 4 consecutive k of one t; no div/mod
__global__ void build_x_kernel(const float* __restrict__ obs, const int* __restrict__ act,
                               const float* __restrict__ emb) {
    int t  = blockIdx.x * 8 + threadIdx.y;
    int k4 = threadIdx.x;                              // 0..23 (k = k4*4)
    float4 v = make_float4(0.f, 0.f, 0.f, 0.f);
    if (k4 < 16) {
        v = *(const float4*)&obs[(size_t)t * 64 + k4 * 4];
    } else if (k4 < 18) {
        int a = act[t];
        v = *(const float4*)&emb[a * 8 + (k4 - 16) * 4];
    }
    __nv_bfloat162 h0 = __float22bfloat162_rn(make_float2(v.x, v.y));
    __nv_bfloat162 h1 = __float22bfloat162_rn(make_float2(v.z, v.w));
    uint2 o = make_uint2(*(uint32_t*)&h0, *(uint32_t*)&h1);
    *(uint2*)&g_A0[(size_t)t * K0PAD + k4 * 4] = o;
}

// ======================= HMMA GEMM + gate epilogue + fused scan-pass1 =========
// CTA: 128(M) x 128(N), BK=32 bf16, 3-stage cp.async, 2 CTAs/SM, single-term bf16.
// SMEM stages: A|W, 128 rows x 32 bf16 each, row stride 80B (10240 B each).
#define STAGE_BYTES 20480
#define PSM_OFF     67584
#define SMEM_BYTES  (67584 + 2048)   // epilogue 128x132 f32 stage + P/S scratch

__device__ __forceinline__ void copy_tile(uint32_t sm, const __nv_bfloat16* g,
                                          int row0, int K, int k0, int tid) {
#pragma unroll
    for (int i = 0; i < 2; i++) {
        int idx = tid + i * 256;
        int row = idx >> 2, seg = idx & 3;
        CP16(sm + row * 80 + seg * 16,
             g + (size_t)(row0 + row) * K + k0 + seg * 8);
    }
}

template <int LAYER>
__global__ void __launch_bounds__(256, 2) gemm_mma_kernel() {
    constexpr int K = (LAYER == 0) ? K0PAD : HID;
    constexpr int NC = K / 32;
    const __nv_bfloat16* __restrict__ A = (LAYER == 0) ? g_A0 : g_A1;
    const __nv_bfloat16* __restrict__ W = (LAYER == 0) ? g_W0 : g_W1;

    extern __shared__ __align__(16) char smem[];
    const uint32_t sb = smem_u32(smem);
    const int tid = threadIdx.x, lane = tid & 31;
    const int wm = (tid >> 5) >> 1, wn = (tid >> 5) & 1;
    const int m0 = blockIdx.y * 128, n0 = blockIdx.x * 128;
    const int q = lane >> 3, r = lane & 7;

    const uint32_t aoff = (uint32_t)(wm * 32 + (q & 1) * 8 + r) * 80 + (q >> 1) * 16;
    const uint32_t woff = 10240u + (uint32_t)(wn * 64 + (q >> 1) * 8 + r) * 80 + (q & 1) * 16;

    float acc[2][8][4];
#pragma unroll
    for (int mt = 0; mt < 2; mt++)
#pragma unroll
        for (int nt = 0; nt < 8; nt++)
#pragma unroll
            for (int i = 0; i < 4; i++) acc[mt][nt][i] = 0.f;

    // prologue: stages 0 and 1
    {
        copy_tile(sb,         A, m0, K, 0, tid);
        copy_tile(sb + 10240, W, n0, K, 0, tid);
        CP_COMMIT();
        copy_tile(sb + STAGE_BYTES,         A, m0, K, 32, tid);
        copy_tile(sb + STAGE_BYTES + 10240, W, n0, K, 32, tid);
        CP_COMMIT();
    }

#pragma unroll
    for (int ck = 0; ck < NC; ck++) {
        if (ck + 2 < NC) {
            uint32_t base = sb + ((ck + 2) % 3) * STAGE_BYTES;
            int k0 = (ck + 2) * 32;
            copy_tile(base,         A, m0, K, k0, tid);
            copy_tile(base + 10240, W, n0, K, k0, tid);
            CP_COMMIT();
            CP_WAIT(2);
        } else if (ck + 1 < NC) {
            CP_WAIT(1);
        } else {
            CP_WAIT(0);
        }
        __syncthreads();

        const uint32_t base = sb + (ck % 3) * STAGE_BYTES;
#pragma unroll
        for (int ks = 0; ks < 2; ks++) {
            uint32_t ah[2][4];
#pragma unroll
            for (int mt = 0; mt < 2; mt++)
                LDSM4(ah[mt], base + aoff + (uint32_t)mt * (16 * 80) + ks * 32);
#pragma unroll
            for (int p = 0; p < 4; p++) {
                uint32_t wh[4];
                LDSM4(wh, base + woff + (uint32_t)p * (16 * 80) + ks * 32);
                const int nt0 = p * 2, nt1 = p * 2 + 1;
                MMA(acc[0][nt0], ah[0], (wh + 0)); MMA(acc[0][nt1], ah[0], (wh + 2));
                MMA(acc[1][nt0], ah[1], (wh + 0)); MMA(acc[1][nt1], ah[1], (wh + 2));
            }
        }
        __syncthreads();
    }

    // ---- epilogue: acc -> SMEM (stride 132) -> gate math + fused pass1 ----
    float* stage = (float*)smem;
#pragma unroll
    for (int mt = 0; mt < 2; mt++)
#pragma unroll
        for (int nt = 0; nt < 8; nt++) {
            int row = wm * 32 + mt * 16 + (lane >> 2);
            int col = wn * 64 + nt * 8 + (lane & 3) * 2;
            stage[row * 132 + col]           = acc[mt][nt][0];
            stage[row * 132 + col + 1]       = acc[mt][nt][1];
            stage[(row + 8) * 132 + col]     = acc[mt][nt][2];
            stage[(row + 8) * 132 + col + 1] = acc[mt][nt][3];
        }
    __syncthreads();

    // thread = (segment = warp, channel = lane); 16 ordered rows per segment
    const int ch  = lane;
    const int seg = tid >> 5;
    const int chg = blockIdx.x * 32 + ch;
    const float na = g_negA[LAYER * HID + chg];
    float p = 1.f, s = 0.f;
#pragma unroll
    for (int j = 0; j < 16; j++) {
        int row = seg * 16 + j;
        float4 v = *(const float4*)&stage[row * 132 + ch * 4];  // xs, B, C, d
        float delta = 1.f / (1.f + expf(-v.w));
        float a  = expf(delta * na);
        float bx = v.y * v.x;
        size_t o = (size_t)(m0 + row) * HID + chg;
        g_abar[o] = a;
        g_bx[o]   = bx;
        g_c[o]    = __float2bfloat16(v.z);
        p *= a;
        s = fmaf(a, s, bx);
    }
    float* psm = (float*)(smem + PSM_OFF);     // [8][32] p, then [8][32] s
    psm[seg * 32 + ch]       = p;
    psm[256 + seg * 32 + ch] = s;
    __syncthreads();
    if (tid < 32) {
        float P = 1.f, S = 0.f;
#pragma unroll
        for (int g = 0; g < 8; g++) {
            float pg = psm[g * 32 + tid], sg = psm[256 + g * 32 + tid];
            S = fmaf(pg, S, sg);
            P *= pg;
        }
        size_t o = (size_t)blockIdx.y * HID + blockIdx.x * 32 + tid;
        g_Ph[o] = P;
        g_Sh[o] = S;
    }
}

// ======================= cross-half scan (512 carries) =======================
__global__ void scan_pass2_kernel() {
    int h = threadIdx.x;
    float acc = 0.f;
#pragma unroll 4
    for (int c = 0; c < NH; c++) {
        g_H0h[c * HID + h] = acc;
        acc = fmaf(g_Ph[c * HID + h], acc, g_Sh[c * HID + h]);
    }
}

// pass3 layer 0: replay 128 steps, emit bf16 for next GEMM
__global__ void scan_pass3_l0_kernel() {
    int h = threadIdx.x, b = blockIdx.x;
    size_t base = (size_t)b * 128 * HID + h;
    float hs = g_H0h[b * HID + h];
#pragma unroll 8
    for (int i = 0; i < 128; i++) {
        size_t o = base + (size_t)i * HID;
        hs = fmaf(g_abar[o], hs, g_bx[o]);
        g_A1[o] = __float2bfloat16(__bfloat162float(g_c[o]) * hs);
    }
}

// pass3 layer 1 + fused output head
__global__ void __launch_bounds__(256) scan_pass3_l1_head_kernel(
        const float* __restrict__ Wout, const float* __restrict__ bout,
        float* __restrict__ out) {
    __shared__ float ws[4 * HID];
    __shared__ float bs4[4];
    __shared__ float yt[32][260];
    int tid = threadIdx.x, lane = tid & 31, w = tid >> 5;
    for (int i = tid; i < 4 * HID; i += 256) ws[i] = Wout[i];
    if (tid < 4) bs4[tid] = bout[tid];

    int h = tid, b = blockIdx.x;
    size_t base = (size_t)b * 128 * HID + h;
    float hs = g_H0h[b * HID + h];
    __syncthreads();

    for (int sub = 0; sub < 4; sub++) {
#pragma unroll 8
        for (int j = 0; j < 32; j++) {
            size_t o = base + (size_t)(sub * 32 + j) * HID;
            hs = fmaf(g_abar[o], hs, g_bx[o]);
            yt[j][h] = __bfloat162float(g_c[o]) * hs;
        }
        __syncthreads();
#pragma unroll
        for (int tt = 0; tt < 4; tt++) {
            int tl = w * 4 + tt;
            float a0 = 0.f, a1 = 0.f, a2 = 0.f, a3 = 0.f;
#pragma unroll
            for (int k = 0; k < 8; k++) {
                float v = yt[tl][k * 32 + lane];
                a0 = fmaf(v, ws[0 * HID + k * 32 + lane], a0);
                a1 = fmaf(v, ws[1 * HID + k * 32 + lane], a1);
                a2 = fmaf(v, ws[2 * HID + k * 32 + lane], a2);
                a3 = fmaf(v, ws[3 * HID + k * 32 + lane], a3);
            }
#pragma unroll
            for (int o2 = 16; o2 > 0; o2 >>= 1) {
                a0 += __shfl_down_sync(0xFFFFFFFFu, a0, o2);
                a1 += __shfl_down_sync(0xFFFFFFFFu, a1, o2);
                a2 += __shfl_down_sync(0xFFFFFFFFu, a2, o2);
                a3 += __shfl_down_sync(0xFFFFFFFFu, a3, o2);
            }
            if (lane == 0) {
                float z[4] = {a0 + bs4[0], a1 + bs4[1], a2 + bs4[2], a3 + bs4[3]};
                size_t t = (size_t)b * 128 + sub * 32 + tl;
#pragma unroll
                for (int o3 = 0; o3 < 4; o3++) {
                    float zz = z[o3];
                    float sp = (zz > 20.f) ? zz : log1pf(expf(zz));
                    out[t * 4 + o3] = sp + 1.f;
                }
            }
        }
        __syncthreads();
    }
}

// ======================= launch =======================
extern "C" void kernel_launch(void* const* d_in, const int* in_sizes, int n_in,
                              void* d_out, int out_size) {
    const float* obs   = (const float*)d_in[0];
    const int*   act   = (const int*)  d_in[1];
    const float* emb   = (const float*)d_in[2];
    const float* Win0  = (const float*)d_in[3];
    const float* WB0   = (const float*)d_in[4];
    const float* WC0   = (const float*)d_in[5];
    const float* Wd0   = (const float*)d_in[6];
    const float* Alog0 = (const float*)d_in[7];
    const float* Win1  = (const float*)d_in[8];
    const float* WB1   = (const float*)d_in[9];
    const float* WC1   = (const float*)d_in[10];
    const float* Wd1   = (const float*)d_in[11];
    const float* Alog1 = (const float*)d_in[12];
    const float* Wout  = (const float*)d_in[13];
    const float* bout  = (const float*)d_in[14];
    float* out = (float*)d_out;

    cudaFuncSetAttribute(gemm_mma_kernel<0>, cudaFuncAttributeMaxDynamicSharedMemorySize, SMEM_BYTES);
    cudaFuncSetAttribute(gemm_mma_kernel<1>, cudaFuncAttributeMaxDynamicSharedMemorySize, SMEM_BYTES);

    prep_w0_kernel<<<(NOUT * K0PAD) / 256, 256>>>(Win0, WB0, WC0, Wd0);
    prep_w1_kernel<<<(NOUT * HID) / 256, 256>>>(Win1, WB1, WC1, Wd1);
    prep_a_kernel<<<1, 256>>>(Alog0, Alog1);
    build_x_kernel<<<T_LEN / 8, dim3(24, 8)>>>(obs, act, emb);

    dim3 ggrid(NOUT / 128, T_LEN / 128);   // (8, 512)

    gemm_mma_kernel<0><<<ggrid, 256, SMEM_BYTES>>>();
    scan_pass2_kernel<<<1, HID>>>();
    scan_pass3_l0_kernel<<<NH, HID>>>();

    gemm_mma_kernel<1><<<ggrid, 256, SMEM_BYTES>>>();
    scan_pass2_kernel<<<1, HID>>>();
    scan_pass3_l1_head_kernel<<<NH, HID>>>(Wout, bout, out);
}

// round 8
// speedup vs baseline: 1.2616x; 1.2616x over previous
#include <cuda_runtime.h>
#include <cuda_bf16.h>
#include <math.h>
#include <stdint.h>

#define T_LEN   65536
#define HID     256
#define K0PAD   96          // layer-0 K (real 72) padded to 3x32
#define IN_RAW  72
#define NOUT    1024        // 4*HID interleaved weight rows
#define NH      (T_LEN / 128)   // 512 half-chunks of 128 timesteps

// ======================= scratch =======================
static __device__ __nv_bfloat16  g_A0[(size_t)T_LEN * K0PAD];
static __device__ __nv_bfloat16  g_A1[(size_t)T_LEN * HID];
static __device__ __nv_bfloat16  g_W0[NOUT * K0PAD];
static __device__ __nv_bfloat16  g_W1[NOUT * HID];
static __device__ __nv_bfloat162 g_ab[(size_t)T_LEN * HID];   // (abar, bx) packed
static __device__ __nv_bfloat16  g_c [(size_t)T_LEN * HID];
static __device__ float g_Ph  [NH * HID];
static __device__ float g_Sh  [NH * HID];
static __device__ float g_H0h [NH * HID];
static __device__ float g_negA[2 * HID];

__device__ __forceinline__ uint32_t smem_u32(const void* p) {
    uint32_t a;
    asm("{ .reg .u64 t; cvta.to.shared.u64 t, %1; cvt.u32.u64 %0, t; }" : "=r"(a) : "l"(p));
    return a;
}

#define CP16(so, gp) \
    asm volatile("cp.async.cg.shared.global [%0], [%1], 16;" :: "r"(so), "l"(gp) : "memory")
#define CP_COMMIT() asm volatile("cp.async.commit_group;" ::: "memory")
#define CP_WAIT(n)  asm volatile("cp.async.wait_group %0;" :: "n"(n) : "memory")

#define LDSM4(r, addr) \
    asm volatile("ldmatrix.sync.aligned.m8n8.x4.shared.b16 {%0,%1,%2,%3}, [%4];" \
        : "=r"((r)[0]), "=r"((r)[1]), "=r"((r)[2]), "=r"((r)[3]) : "r"(addr))

// non-volatile: lets ptxas schedule/interleave MMAs
#define MMA(d, a, b) \
    asm("mma.sync.aligned.m16n8k16.row.col.f32.bf16.bf16.f32 " \
        "{%0,%1,%2,%3}, {%4,%5,%6,%7}, {%8,%9}, {%0,%1,%2,%3};" \
        : "+f"((d)[0]), "+f"((d)[1]), "+f"((d)[2]), "+f"((d)[3]) \
        : "r"((a)[0]), "r"((a)[1]), "r"((a)[2]), "r"((a)[3]), \
          "r"((b)[0]), "r"((b)[1]))

// ======================= prep =======================
__global__ void prep_w0_kernel(const float* __restrict__ Win, const float* __restrict__ WB,
                               const float* __restrict__ WC, const float* __restrict__ Wd) {
    int idx = blockIdx.x * 256 + threadIdx.x;          // NOUT*K0PAD
    int r = idx / K0PAD, k = idx % K0PAD;
    int h = r >> 2, j = r & 3;
    float v = 0.f;
    if (k < IN_RAW) {
        const float* s = (j == 0) ? Win : (j == 1) ? WB : (j == 2) ? WC : Wd;
        v = s[h * IN_RAW + k];
    }
    g_W0[idx] = __float2bfloat16(v);
}

__global__ void prep_w1_kernel(const float* __restrict__ Win, const float* __restrict__ WB,
                               const float* __restrict__ WC, const float* __restrict__ Wd) {
    int idx = blockIdx.x * 256 + threadIdx.x;          // NOUT*HID
    int r = idx / HID, k = idx % HID;
    int h = r >> 2, j = r & 3;
    const float* s = (j == 0) ? Win : (j == 1) ? WB : (j == 2) ? WC : Wd;
    g_W1[idx] = __float2bfloat16(s[h * HID + k]);
}

__global__ void prep_a_kernel(const float* __restrict__ A0, const float* __restrict__ A1) {
    int h = threadIdx.x;
    g_negA[h] = -expf(A0[h]);
    g_negA[HID + h] = -expf(A1[h]);
}

// 2D vectorized: block (24, 8); thread = 4 consecutive k of one t; no div/mod
__global__ void build_x_kernel(const float* __restrict__ obs, const int* __restrict__ act,
                               const float* __restrict__ emb) {
    int t  = blockIdx.x * 8 + threadIdx.y;
    int k4 = threadIdx.x;                              // 0..23 (k = k4*4)
    float4 v = make_float4(0.f, 0.f, 0.f, 0.f);
    if (k4 < 16) {
        v = *(const float4*)&obs[(size_t)t * 64 + k4 * 4];
    } else if (k4 < 18) {
        int a = act[t];
        v = *(const float4*)&emb[a * 8 + (k4 - 16) * 4];
    }
    __nv_bfloat162 h0 = __float22bfloat162_rn(make_float2(v.x, v.y));
    __nv_bfloat162 h1 = __float22bfloat162_rn(make_float2(v.z, v.w));
    uint2 o = make_uint2(*(uint32_t*)&h0, *(uint32_t*)&h1);
    *(uint2*)&g_A0[(size_t)t * K0PAD + k4 * 4] = o;
}

// ======================= HMMA GEMM + gate epilogue (round-6 proven config) ====
// CTA: 128(M) x 128(N), BK=32 bf16, 2-stage cp.async, 2 CTAs/SM, single-term bf16.
// SMEM stage: A|W, 128 rows x 32 bf16 each, row stride 80B (10240 B each).
#define STAGE_BYTES 20480
#define SMEM_BYTES  67584   // epilogue stage 128x132 f32 dominates

__device__ __forceinline__ void copy_tile(uint32_t sm, const __nv_bfloat16* g,
                                          int row0, int K, int k0, int tid) {
#pragma unroll
    for (int i = 0; i < 2; i++) {
        int idx = tid + i * 256;
        int row = idx >> 2, seg = idx & 3;
        CP16(sm + row * 80 + seg * 16,
             g + (size_t)(row0 + row) * K + k0 + seg * 8);
    }
}

template <int LAYER>
__global__ void __launch_bounds__(256, 2) gemm_mma_kernel() {
    constexpr int K = (LAYER == 0) ? K0PAD : HID;
    constexpr int NC = K / 32;
    const __nv_bfloat16* __restrict__ A = (LAYER == 0) ? g_A0 : g_A1;
    const __nv_bfloat16* __restrict__ W = (LAYER == 0) ? g_W0 : g_W1;

    extern __shared__ __align__(16) char smem[];
    const uint32_t sb = smem_u32(smem);
    const int tid = threadIdx.x, lane = tid & 31;
    const int wm = (tid >> 5) >> 1, wn = (tid >> 5) & 1;
    const int m0 = blockIdx.y * 128, n0 = blockIdx.x * 128;
    const int q = lane >> 3, r = lane & 7;

    const uint32_t aoff = (uint32_t)(wm * 32 + (q & 1) * 8 + r) * 80 + (q >> 1) * 16;
    const uint32_t woff = 10240u + (uint32_t)(wn * 64 + (q >> 1) * 8 + r) * 80 + (q & 1) * 16;

    float acc[2][8][4];
#pragma unroll
    for (int mt = 0; mt < 2; mt++)
#pragma unroll
        for (int nt = 0; nt < 8; nt++)
#pragma unroll
            for (int i = 0; i < 4; i++) acc[mt][nt][i] = 0.f;

    // prologue: stage 0
    {
        copy_tile(sb,         A, m0, K, 0, tid);
        copy_tile(sb + 10240, W, n0, K, 0, tid);
        CP_COMMIT();
    }

    for (int ck = 0; ck < NC; ck++) {
        if (ck + 1 < NC) {
            uint32_t base = sb + ((ck + 1) & 1) * STAGE_BYTES;
            int k0 = (ck + 1) * 32;
            copy_tile(base,         A, m0, K, k0, tid);
            copy_tile(base + 10240, W, n0, K, k0, tid);
            CP_COMMIT();
            CP_WAIT(1);
        } else {
            CP_WAIT(0);
        }
        __syncthreads();

        const uint32_t base = sb + (ck & 1) * STAGE_BYTES;
#pragma unroll
        for (int ks = 0; ks < 2; ks++) {
            uint32_t ah[2][4];
#pragma unroll
            for (int mt = 0; mt < 2; mt++)
                LDSM4(ah[mt], base + aoff + (uint32_t)mt * (16 * 80) + ks * 32);
#pragma unroll
            for (int p = 0; p < 4; p++) {
                uint32_t wh[4];
                LDSM4(wh, base + woff + (uint32_t)p * (16 * 80) + ks * 32);
                const int nt0 = p * 2, nt1 = p * 2 + 1;
                MMA(acc[0][nt0], ah[0], (wh + 0)); MMA(acc[0][nt1], ah[0], (wh + 2));
                MMA(acc[1][nt0], ah[1], (wh + 0)); MMA(acc[1][nt1], ah[1], (wh + 2));
            }
        }
        __syncthreads();
    }

    // ---- epilogue: acc -> SMEM (stride 132) -> gate math -> packed stores ----
    float* stage = (float*)smem;
#pragma unroll
    for (int mt = 0; mt < 2; mt++)
#pragma unroll
        for (int nt = 0; nt < 8; nt++) {
            int row = wm * 32 + mt * 16 + (lane >> 2);
            int col = wn * 64 + nt * 8 + (lane & 3) * 2;
            stage[row * 132 + col]           = acc[mt][nt][0];
            stage[row * 132 + col + 1]       = acc[mt][nt][1];
            stage[(row + 8) * 132 + col]     = acc[mt][nt][2];
            stage[(row + 8) * 132 + col + 1] = acc[mt][nt][3];
        }
    __syncthreads();

    const int chl = tid & 31;
    const int rb = tid >> 5;
    const int chg = blockIdx.x * 32 + chl;             // CTA covers 32 channels
    const float na = g_negA[LAYER * HID + chg];
#pragma unroll
    for (int i = 0; i < 16; i++) {
        int row = rb + i * 8;
        float4 v = *(const float4*)&stage[row * 132 + chl * 4];  // xs, B, C, d
        float delta = 1.f / (1.f + expf(-v.w));
        float a  = expf(delta * na);
        float bx = v.y * v.x;
        size_t o = (size_t)(m0 + row) * HID + chg;
        g_ab[o] = __floats2bfloat162_rn(a, bx);
        g_c[o]  = __float2bfloat16(v.z);
    }
}

// ======================= chunked scan (512 half-chunks x 128 steps) ===========
__global__ void scan_pass1_kernel() {
    int h = threadIdx.x, b = blockIdx.x;
    size_t base = (size_t)b * 128 * HID + h;
    float p = 1.f, s = 0.f;
#pragma unroll 8
    for (int i = 0; i < 128; i++) {
        float2 f = __bfloat1622float2(g_ab[base + (size_t)i * HID]);
        p *= f.x;
        s = fmaf(f.x, s, f.y);
    }
    g_Ph[b * HID + h] = p;
    g_Sh[b * HID + h] = s;
}

__global__ void scan_pass2_kernel() {
    int h = threadIdx.x;
    float acc = 0.f;
#pragma unroll 4
    for (int c = 0; c < NH; c++) {
        g_H0h[c * HID + h] = acc;
        acc = fmaf(g_Ph[c * HID + h], acc, g_Sh[c * HID + h]);
    }
}

// pass3 layer 0: replay 128 steps, emit bf16 for next GEMM
__global__ void scan_pass3_l0_kernel() {
    int h = threadIdx.x, b = blockIdx.x;
    size_t base = (size_t)b * 128 * HID + h;
    float hs = g_H0h[b * HID + h];
#pragma unroll 8
    for (int i = 0; i < 128; i++) {
        size_t o = base + (size_t)i * HID;
        float2 f = __bfloat1622float2(g_ab[o]);
        hs = fmaf(f.x, hs, f.y);
        g_A1[o] = __float2bfloat16(__bfloat162float(g_c[o]) * hs);
    }
}

// pass3 layer 1 + fused output head
__global__ void __launch_bounds__(256) scan_pass3_l1_head_kernel(
        const float* __restrict__ Wout, const float* __restrict__ bout,
        float* __restrict__ out) {
    __shared__ float ws[4 * HID];
    __shared__ float bs4[4];
    __shared__ float yt[32][260];
    int tid = threadIdx.x, lane = tid & 31, w = tid >> 5;
    for (int i = tid; i < 4 * HID; i += 256) ws[i] = Wout[i];
    if (tid < 4) bs4[tid] = bout[tid];

    int h = tid, b = blockIdx.x;
    size_t base = (size_t)b * 128 * HID + h;
    float hs = g_H0h[b * HID + h];
    __syncthreads();

    for (int sub = 0; sub < 4; sub++) {
#pragma unroll 8
        for (int j = 0; j < 32; j++) {
            size_t o = base + (size_t)(sub * 32 + j) * HID;
            float2 f = __bfloat1622float2(g_ab[o]);
            hs = fmaf(f.x, hs, f.y);
            yt[j][h] = __bfloat162float(g_c[o]) * hs;
        }
        __syncthreads();
#pragma unroll
        for (int tt = 0; tt < 4; tt++) {
            int tl = w * 4 + tt;
            float a0 = 0.f, a1 = 0.f, a2 = 0.f, a3 = 0.f;
#pragma unroll
            for (int k = 0; k < 8; k++) {
                float v = yt[tl][k * 32 + lane];
                a0 = fmaf(v, ws[0 * HID + k * 32 + lane], a0);
                a1 = fmaf(v, ws[1 * HID + k * 32 + lane], a1);
                a2 = fmaf(v, ws[2 * HID + k * 32 + lane], a2);
                a3 = fmaf(v, ws[3 * HID + k * 32 + lane], a3);
            }
#pragma unroll
            for (int o2 = 16; o2 > 0; o2 >>= 1) {
                a0 += __shfl_down_sync(0xFFFFFFFFu, a0, o2);
                a1 += __shfl_down_sync(0xFFFFFFFFu, a1, o2);
                a2 += __shfl_down_sync(0xFFFFFFFFu, a2, o2);
                a3 += __shfl_down_sync(0xFFFFFFFFu, a3, o2);
            }
            if (lane == 0) {
                float z[4] = {a0 + bs4[0], a1 + bs4[1], a2 + bs4[2], a3 + bs4[3]};
                size_t t = (size_t)b * 128 + sub * 32 + tl;
#pragma unroll
                for (int o3 = 0; o3 < 4; o3++) {
                    float zz = z[o3];
                    float sp = (zz > 20.f) ? zz : log1pf(expf(zz));
                    out[t * 4 + o3] = sp + 1.f;
                }
            }
        }
        __syncthreads();
    }
}

// ======================= launch =======================
extern "C" void kernel_launch(void* const* d_in, const int* in_sizes, int n_in,
                              void* d_out, int out_size) {
    const float* obs   = (const float*)d_in[0];
    const int*   act   = (const int*)  d_in[1];
    const float* emb   = (const float*)d_in[2];
    const float* Win0  = (const float*)d_in[3];
    const float* WB0   = (const float*)d_in[4];
    const float* WC0   = (const float*)d_in[5];
    const float* Wd0   = (const float*)d_in[6];
    const float* Alog0 = (const float*)d_in[7];
    const float* Win1  = (const float*)d_in[8];
    const float* WB1   = (const float*)d_in[9];
    const float* WC1   = (const float*)d_in[10];
    const float* Wd1   = (const float*)d_in[11];
    const float* Alog1 = (const float*)d_in[12];
    const float* Wout  = (const float*)d_in[13];
    const float* bout  = (const float*)d_in[14];
    float* out = (float*)d_out;

    cudaFuncSetAttribute(gemm_mma_kernel<0>, cudaFuncAttributeMaxDynamicSharedMemorySize, SMEM_BYTES);
    cudaFuncSetAttribute(gemm_mma_kernel<1>, cudaFuncAttributeMaxDynamicSharedMemorySize, SMEM_BYTES);

    prep_w0_kernel<<<(NOUT * K0PAD) / 256, 256>>>(Win0, WB0, WC0, Wd0);
    prep_w1_kernel<<<(NOUT * HID) / 256, 256>>>(Win1, WB1, WC1, Wd1);
    prep_a_kernel<<<1, 256>>>(Alog0, Alog1);
    build_x_kernel<<<T_LEN / 8, dim3(24, 8)>>>(obs, act, emb);

    dim3 ggrid(NOUT / 128, T_LEN / 128);   // (8, 512)

    gemm_mma_kernel<0><<<ggrid, 256, SMEM_BYTES>>>();
    scan_pass1_kernel<<<NH, HID>>>();
    scan_pass2_kernel<<<1, HID>>>();
    scan_pass3_l0_kernel<<<NH, HID>>>();

    gemm_mma_kernel<1><<<ggrid, 256, SMEM_BYTES>>>();
    scan_pass1_kernel<<<NH, HID>>>();
    scan_pass2_kernel<<<1, HID>>>();
    scan_pass3_l1_head_kernel<<<NH, HID>>>(Wout, bout, out);
}

// round 9
// speedup vs baseline: 1.9309x; 1.5306x over previous
#include <cuda_runtime.h>
#include <cuda_bf16.h>
#include <math.h>
#include <stdint.h>

#define T_LEN   65536
#define HID     256
#define K0PAD   96          // layer-0 K (real 72) padded to 3x32
#define IN_RAW  72
#define NOUT    1024        // 4*HID interleaved weight rows
#define NH      (T_LEN / 128)   // 512 half-chunks of 128 timesteps
#define NGRP    16              // 16 groups of 32 half-chunks

// ======================= scratch =======================
static __device__ __nv_bfloat16  g_A0[(size_t)T_LEN * K0PAD];
static __device__ __nv_bfloat16  g_A1[(size_t)T_LEN * HID];
static __device__ __nv_bfloat16  g_W0[NOUT * K0PAD];
static __device__ __nv_bfloat16  g_W1[NOUT * HID];
static __device__ __nv_bfloat162 g_ab[(size_t)T_LEN * HID];   // (abar, bx) packed
static __device__ __nv_bfloat16  g_c [(size_t)T_LEN * HID];
static __device__ float g_Ph[NH * HID];
static __device__ float g_Sh[NH * HID];
static __device__ float g_Lp[NH * HID];      // within-group prefix product
static __device__ float g_Ls[NH * HID];      // within-group prefix state
static __device__ float g_GP[NGRP * HID];    // group total product
static __device__ float g_GS[NGRP * HID];    // group total state
static __device__ float g_G0[NGRP * HID];    // state at group start
static __device__ float g_negA[2 * HID];

__device__ __forceinline__ uint32_t smem_u32(const void* p) {
    uint32_t a;
    asm("{ .reg .u64 t; cvta.to.shared.u64 t, %1; cvt.u32.u64 %0, t; }" : "=r"(a) : "l"(p));
    return a;
}

#define CP16(so, gp) \
    asm volatile("cp.async.cg.shared.global [%0], [%1], 16;" :: "r"(so), "l"(gp) : "memory")
#define CP_COMMIT() asm volatile("cp.async.commit_group;" ::: "memory")
#define CP_WAIT(n)  asm volatile("cp.async.wait_group %0;" :: "n"(n) : "memory")

#define LDSM4(r, addr) \
    asm volatile("ldmatrix.sync.aligned.m8n8.x4.shared.b16 {%0,%1,%2,%3}, [%4];" \
        : "=r"((r)[0]), "=r"((r)[1]), "=r"((r)[2]), "=r"((r)[3]) : "r"(addr))

// non-volatile: lets ptxas schedule/interleave MMAs
#define MMA(d, a, b) \
    asm("mma.sync.aligned.m16n8k16.row.col.f32.bf16.bf16.f32 " \
        "{%0,%1,%2,%3}, {%4,%5,%6,%7}, {%8,%9}, {%0,%1,%2,%3};" \
        : "+f"((d)[0]), "+f"((d)[1]), "+f"((d)[2]), "+f"((d)[3]) \
        : "r"((a)[0]), "r"((a)[1]), "r"((a)[2]), "r"((a)[3]), \
          "r"((b)[0]), "r"((b)[1]))

// ======================= prep =======================
__global__ void prep_w0_kernel(const float* __restrict__ Win, const float* __restrict__ WB,
                               const float* __restrict__ WC, const float* __restrict__ Wd) {
    int idx = blockIdx.x * 256 + threadIdx.x;          // NOUT*K0PAD
    int r = idx / K0PAD, k = idx % K0PAD;
    int h = r >> 2, j = r & 3;
    float v = 0.f;
    if (k < IN_RAW) {
        const float* s = (j == 0) ? Win : (j == 1) ? WB : (j == 2) ? WC : Wd;
        v = s[h * IN_RAW + k];
    }
    g_W0[idx] = __float2bfloat16(v);
}

__global__ void prep_w1_kernel(const float* __restrict__ Win, const float* __restrict__ WB,
                               const float* __restrict__ WC, const float* __restrict__ Wd) {
    int idx = blockIdx.x * 256 + threadIdx.x;          // NOUT*HID
    int r = idx / HID, k = idx % HID;
    int h = r >> 2, j = r & 3;
    const float* s = (j == 0) ? Win : (j == 1) ? WB : (j == 2) ? WC : Wd;
    g_W1[idx] = __float2bfloat16(s[h * HID + k]);
}

__global__ void prep_a_kernel(const float* __restrict__ A0, const float* __restrict__ A1) {
    int h = threadIdx.x;
    g_negA[h] = -expf(A0[h]);
    g_negA[HID + h] = -expf(A1[h]);
}

// 2D vectorized: block (24, 8); thread = 4 consecutive k of one t; no div/mod
__global__ void build_x_kernel(const float* __restrict__ obs, const int* __restrict__ act,
                               const float* __restrict__ emb) {
    int t  = blockIdx.x * 8 + threadIdx.y;
    int k4 = threadIdx.x;                              // 0..23 (k = k4*4)
    float4 v = make_float4(0.f, 0.f, 0.f, 0.f);
    if (k4 < 16) {
        v = *(const float4*)&obs[(size_t)t * 64 + k4 * 4];
    } else if (k4 < 18) {
        int a = act[t];
        v = *(const float4*)&emb[a * 8 + (k4 - 16) * 4];
    }
    __nv_bfloat162 h0 = __float22bfloat162_rn(make_float2(v.x, v.y));
    __nv_bfloat162 h1 = __float22bfloat162_rn(make_float2(v.z, v.w));
    uint2 o = make_uint2(*(uint32_t*)&h0, *(uint32_t*)&h1);
    *(uint2*)&g_A0[(size_t)t * K0PAD + k4 * 4] = o;
}

// ======================= HMMA GEMM + gate epilogue =======================
// CTA: 128(M) x 128(N), BK=32 bf16, 3-stage cp.async with ONE sync per chunk,
// 2 CTAs/SM, single-term bf16.
// SMEM stage: A|W, 128 rows x 32 bf16 each, row stride 80B (10240 B each).
#define STAGE_BYTES 20480
#define SMEM_BYTES  67584   // max(3*20480, epilogue 128x132 f32 stage)

__device__ __forceinline__ void copy_tile(uint32_t sm, const __nv_bfloat16* g,
                                          int row0, int K, int k0, int tid) {
#pragma unroll
    for (int i = 0; i < 2; i++) {
        int idx = tid + i * 256;
        int row = idx >> 2, seg = idx & 3;
        CP16(sm + row * 80 + seg * 16,
             g + (size_t)(row0 + row) * K + k0 + seg * 8);
    }
}

template <int LAYER>
__global__ void __launch_bounds__(256, 2) gemm_mma_kernel() {
    constexpr int K = (LAYER == 0) ? K0PAD : HID;
    constexpr int NC = K / 32;
    const __nv_bfloat16* __restrict__ A = (LAYER == 0) ? g_A0 : g_A1;
    const __nv_bfloat16* __restrict__ W = (LAYER == 0) ? g_W0 : g_W1;

    extern __shared__ __align__(16) char smem[];
    const uint32_t sb = smem_u32(smem);
    const int tid = threadIdx.x, lane = tid & 31;
    const int wm = (tid >> 5) >> 1, wn = (tid >> 5) & 1;
    const int m0 = blockIdx.y * 128, n0 = blockIdx.x * 128;
    const int q = lane >> 3, r = lane & 7;

    const uint32_t aoff = (uint32_t)(wm * 32 + (q & 1) * 8 + r) * 80 + (q >> 1) * 16;
    const uint32_t woff = 10240u + (uint32_t)(wn * 64 + (q >> 1) * 8 + r) * 80 + (q & 1) * 16;

    float acc[2][8][4];
#pragma unroll
    for (int mt = 0; mt < 2; mt++)
#pragma unroll
        for (int nt = 0; nt < 8; nt++)
#pragma unroll
            for (int i = 0; i < 4; i++) acc[mt][nt][i] = 0.f;

    // prologue: stages 0, 1
    {
        copy_tile(sb,         A, m0, K, 0, tid);
        copy_tile(sb + 10240, W, n0, K, 0, tid);
        CP_COMMIT();
        copy_tile(sb + STAGE_BYTES,         A, m0, K, 32, tid);
        copy_tile(sb + STAGE_BYTES + 10240, W, n0, K, 32, tid);
        CP_COMMIT();
    }

    for (int ck = 0; ck < NC; ck++) {
        if (ck + 1 < NC) { CP_WAIT(1); } else { CP_WAIT(0); }
        __syncthreads();   // all warps done with buf[(ck-1)%3]; buf[ck%3] ready
        if (ck + 2 < NC) {
            uint32_t nbase = sb + ((ck + 2) % 3) * STAGE_BYTES;
            int k0 = (ck + 2) * 32;
            copy_tile(nbase,         A, m0, K, k0, tid);
            copy_tile(nbase + 10240, W, n0, K, k0, tid);
            CP_COMMIT();
        }

        const uint32_t base = sb + (ck % 3) * STAGE_BYTES;
#pragma unroll
        for (int ks = 0; ks < 2; ks++) {
            uint32_t ah[2][4];
#pragma unroll
            for (int mt = 0; mt < 2; mt++)
                LDSM4(ah[mt], base + aoff + (uint32_t)mt * (16 * 80) + ks * 32);
#pragma unroll
            for (int p = 0; p < 4; p++) {
                uint32_t wh[4];
                LDSM4(wh, base + woff + (uint32_t)p * (16 * 80) + ks * 32);
                const int nt0 = p * 2, nt1 = p * 2 + 1;
                MMA(acc[0][nt0], ah[0], (wh + 0)); MMA(acc[0][nt1], ah[0], (wh + 2));
                MMA(acc[1][nt0], ah[1], (wh + 0)); MMA(acc[1][nt1], ah[1], (wh + 2));
            }
        }
    }
    __syncthreads();   // protect epilogue smem reuse

    // ---- epilogue: acc -> SMEM (stride 132) -> gate math -> packed stores ----
    float* stage = (float*)smem;
#pragma unroll
    for (int mt = 0; mt < 2; mt++)
#pragma unroll
        for (int nt = 0; nt < 8; nt++) {
            int row = wm * 32 + mt * 16 + (lane >> 2);
            int col = wn * 64 + nt * 8 + (lane & 3) * 2;
            stage[row * 132 + col]           = acc[mt][nt][0];
            stage[row * 132 + col + 1]       = acc[mt][nt][1];
            stage[(row + 8) * 132 + col]     = acc[mt][nt][2];
            stage[(row + 8) * 132 + col + 1] = acc[mt][nt][3];
        }
    __syncthreads();

    const int chl = tid & 31;
    const int rb = tid >> 5;
    const int chg = blockIdx.x * 32 + chl;             // CTA covers 32 channels
    const float na = g_negA[LAYER * HID + chg];
#pragma unroll
    for (int i = 0; i < 16; i++) {
        int row = rb + i * 8;
        float4 v = *(const float4*)&stage[row * 132 + chl * 4];  // xs, B, C, d
        float delta = 1.f / (1.f + expf(-v.w));
        float a  = expf(delta * na);
        float bx = v.y * v.x;
        size_t o = (size_t)(m0 + row) * HID + chg;
        g_ab[o] = __floats2bfloat162_rn(a, bx);
        g_c[o]  = __float2bfloat16(v.z);
    }
}

// ======================= chunked scan =======================
// pass1: per half-chunk (128 steps) totals
__global__ void scan_pass1_kernel() {
    int h = threadIdx.x, b = blockIdx.x;
    size_t base = (size_t)b * 128 * HID + h;
    float p = 1.f, s = 0.f;
#pragma unroll 8
    for (int i = 0; i < 128; i++) {
        float2 f = __bfloat1622float2(g_ab[base + (size_t)i * HID]);
        p *= f.x;
        s = fmaf(f.x, s, f.y);
    }
    g_Ph[b * HID + h] = p;
    g_Sh[b * HID + h] = s;
}

// pass2a: 16 groups x 32 half-chunks — within-group prefix + totals
__global__ void scan_pass2a_kernel() {
    int h = threadIdx.x, g = blockIdx.x;
    float lp = 1.f, ls = 0.f;
#pragma unroll 4
    for (int j = 0; j < 32; j++) {
        int c = g * 32 + j;
        g_Lp[c * HID + h] = lp;
        g_Ls[c * HID + h] = ls;
        float p = g_Ph[c * HID + h], s = g_Sh[c * HID + h];
        ls = fmaf(p, ls, s);
        lp *= p;
    }
    g_GP[g * HID + h] = lp;
    g_GS[g * HID + h] = ls;
}

// pass2b: serial scan over 16 group carries
__global__ void scan_pass2b_kernel() {
    int h = threadIdx.x;
    float acc = 0.f;
#pragma unroll
    for (int g = 0; g < NGRP; g++) {
        g_G0[g * HID + h] = acc;
        acc = fmaf(g_GP[g * HID + h], acc, g_GS[g * HID + h]);
    }
}

// pass3 layer 0: h0 = Lp*G0 + Ls, replay 128 steps, emit bf16 for next GEMM
__global__ void scan_pass3_l0_kernel() {
    int h = threadIdx.x, b = blockIdx.x;
    size_t base = (size_t)b * 128 * HID + h;
    float hs = fmaf(g_Lp[b * HID + h], g_G0[(b >> 5) * HID + h], g_Ls[b * HID + h]);
#pragma unroll 8
    for (int i = 0; i < 128; i++) {
        size_t o = base + (size_t)i * HID;
        float2 f = __bfloat1622float2(g_ab[o]);
        hs = fmaf(f.x, hs, f.y);
        g_A1[o] = __float2bfloat16(__bfloat162float(g_c[o]) * hs);
    }
}

// pass3 layer 1 + fused output head
__global__ void __launch_bounds__(256) scan_pass3_l1_head_kernel(
        const float* __restrict__ Wout, const float* __restrict__ bout,
        float* __restrict__ out) {
    __shared__ float ws[4 * HID];
    __shared__ float bs4[4];
    __shared__ float yt[32][260];
    int tid = threadIdx.x, lane = tid & 31, w = tid >> 5;
    for (int i = tid; i < 4 * HID; i += 256) ws[i] = Wout[i];
    if (tid < 4) bs4[tid] = bout[tid];

    int h = tid, b = blockIdx.x;
    size_t base = (size_t)b * 128 * HID + h;
    float hs = fmaf(g_Lp[b * HID + h], g_G0[(b >> 5) * HID + h], g_Ls[b * HID + h]);
    __syncthreads();

    for (int sub = 0; sub < 4; sub++) {
#pragma unroll 8
        for (int j = 0; j < 32; j++) {
            size_t o = base + (size_t)(sub * 32 + j) * HID;
            float2 f = __bfloat1622float2(g_ab[o]);
            hs = fmaf(f.x, hs, f.y);
            yt[j][h] = __bfloat162float(g_c[o]) * hs;
        }
        __syncthreads();
#pragma unroll
        for (int tt = 0; tt < 4; tt++) {
            int tl = w * 4 + tt;
            float a0 = 0.f, a1 = 0.f, a2 = 0.f, a3 = 0.f;
#pragma unroll
            for (int k = 0; k < 8; k++) {
                float v = yt[tl][k * 32 + lane];
                a0 = fmaf(v, ws[0 * HID + k * 32 + lane], a0);
                a1 = fmaf(v, ws[1 * HID + k * 32 + lane], a1);
                a2 = fmaf(v, ws[2 * HID + k * 32 + lane], a2);
                a3 = fmaf(v, ws[3 * HID + k * 32 + lane], a3);
            }
#pragma unroll
            for (int o2 = 16; o2 > 0; o2 >>= 1) {
                a0 += __shfl_down_sync(0xFFFFFFFFu, a0, o2);
                a1 += __shfl_down_sync(0xFFFFFFFFu, a1, o2);
                a2 += __shfl_down_sync(0xFFFFFFFFu, a2, o2);
                a3 += __shfl_down_sync(0xFFFFFFFFu, a3, o2);
            }
            if (lane == 0) {
                float z[4] = {a0 + bs4[0], a1 + bs4[1], a2 + bs4[2], a3 + bs4[3]};
                size_t t = (size_t)b * 128 + sub * 32 + tl;
#pragma unroll
                for (int o3 = 0; o3 < 4; o3++) {
                    float zz = z[o3];
                    float sp = (zz > 20.f) ? zz : log1pf(expf(zz));
                    out[t * 4 + o3] = sp + 1.f;
                }
            }
        }
        __syncthreads();
    }
}

// ======================= launch =======================
extern "C" void kernel_launch(void* const* d_in, const int* in_sizes, int n_in,
                              void* d_out, int out_size) {
    const float* obs   = (const float*)d_in[0];
    const int*   act   = (const int*)  d_in[1];
    const float* emb   = (const float*)d_in[2];
    const float* Win0  = (const float*)d_in[3];
    const float* WB0   = (const float*)d_in[4];
    const float* WC0   = (const float*)d_in[5];
    const float* Wd0   = (const float*)d_in[6];
    const float* Alog0 = (const float*)d_in[7];
    const float* Win1  = (const float*)d_in[8];
    const float* WB1   = (const float*)d_in[9];
    const float* WC1   = (const float*)d_in[10];
    const float* Wd1   = (const float*)d_in[11];
    const float* Alog1 = (const float*)d_in[12];
    const float* Wout  = (const float*)d_in[13];
    const float* bout  = (const float*)d_in[14];
    float* out = (float*)d_out;

    cudaFuncSetAttribute(gemm_mma_kernel<0>, cudaFuncAttributeMaxDynamicSharedMemorySize, SMEM_BYTES);
    cudaFuncSetAttribute(gemm_mma_kernel<1>, cudaFuncAttributeMaxDynamicSharedMemorySize, SMEM_BYTES);

    prep_w0_kernel<<<(NOUT * K0PAD) / 256, 256>>>(Win0, WB0, WC0, Wd0);
    prep_w1_kernel<<<(NOUT * HID) / 256, 256>>>(Win1, WB1, WC1, Wd1);
    prep_a_kernel<<<1, 256>>>(Alog0, Alog1);
    build_x_kernel<<<T_LEN / 8, dim3(24, 8)>>>(obs, act, emb);

    dim3 ggrid(NOUT / 128, T_LEN / 128);   // (8, 512)

    gemm_mma_kernel<0><<<ggrid, 256, SMEM_BYTES>>>();
    scan_pass1_kernel<<<NH, HID>>>();
    scan_pass2a_kernel<<<NGRP, HID>>>();
    scan_pass2b_kernel<<<1, HID>>>();
    scan_pass3_l0_kernel<<<NH, HID>>>();

    gemm_mma_kernel<1><<<ggrid, 256, SMEM_BYTES>>>();
    scan_pass1_kernel<<<NH, HID>>>();
    scan_pass2a_kernel<<<NGRP, HID>>>();
    scan_pass2b_kernel<<<1, HID>>>();
    scan_pass3_l1_head_kernel<<<NH, HID>>>(Wout, bout, out);
}

// round 10
// speedup vs baseline: 1.9645x; 1.0174x over previous
#include <cuda_runtime.h>
#include <cuda_bf16.h>
#include <math.h>
#include <stdint.h>

#define T_LEN   65536
#define HID     256
#define K0PAD   96          // layer-0 K (real 72) padded
#define IN_RAW  72
#define NOUT    1024        // 4*HID interleaved weight rows
#define NH      (T_LEN / 128)   // 512 half-chunks of 128 timesteps
#define NGRP    16              // 16 groups of 32 half-chunks

// ======================= scratch =======================
static __device__ __nv_bfloat16  g_A0[(size_t)T_LEN * K0PAD];
static __device__ __nv_bfloat16  g_A1[(size_t)T_LEN * HID];
static __device__ __nv_bfloat16  g_W0[NOUT * K0PAD];
static __device__ __nv_bfloat16  g_W1[NOUT * HID];
static __device__ __nv_bfloat162 g_ab[(size_t)T_LEN * HID];   // (abar, bx) packed
static __device__ __nv_bfloat16  g_c [(size_t)T_LEN * HID];
static __device__ float g_Ph[NH * HID];
static __device__ float g_Sh[NH * HID];
static __device__ float g_Lp[NH * HID];
static __device__ float g_Ls[NH * HID];
static __device__ float g_GP[NGRP * HID];
static __device__ float g_GS[NGRP * HID];
static __device__ float g_G0[NGRP * HID];
static __device__ float g_negA[2 * HID];

__device__ __forceinline__ uint32_t smem_u32(const void* p) {
    uint32_t a;
    asm("{ .reg .u64 t; cvta.to.shared.u64 t, %1; cvt.u32.u64 %0, t; }" : "=r"(a) : "l"(p));
    return a;
}

#define CP16(so, gp) \
    asm volatile("cp.async.cg.shared.global [%0], [%1], 16;" :: "r"(so), "l"(gp) : "memory")
#define CP_COMMIT() asm volatile("cp.async.commit_group;" ::: "memory")
#define CP_WAIT(n)  asm volatile("cp.async.wait_group %0;" :: "n"(n) : "memory")

#define LDSM4(r, addr) \
    asm volatile("ldmatrix.sync.aligned.m8n8.x4.shared.b16 {%0,%1,%2,%3}, [%4];" \
        : "=r"((r)[0]), "=r"((r)[1]), "=r"((r)[2]), "=r"((r)[3]) : "r"(addr))

// non-volatile: lets ptxas schedule/interleave MMAs
#define MMA(d, a, b) \
    asm("mma.sync.aligned.m16n8k16.row.col.f32.bf16.bf16.f32 " \
        "{%0,%1,%2,%3}, {%4,%5,%6,%7}, {%8,%9}, {%0,%1,%2,%3};" \
        : "+f"((d)[0]), "+f"((d)[1]), "+f"((d)[2]), "+f"((d)[3]) \
        : "r"((a)[0]), "r"((a)[1]), "r"((a)[2]), "r"((a)[3]), \
          "r"((b)[0]), "r"((b)[1]))

// ======================= prep =======================
__global__ void prep_w0_kernel(const float* __restrict__ Win, const float* __restrict__ WB,
                               const float* __restrict__ WC, const float* __restrict__ Wd) {
    int idx = blockIdx.x * 256 + threadIdx.x;          // NOUT*K0PAD
    int r = idx / K0PAD, k = idx % K0PAD;
    int h = r >> 2, j = r & 3;
    float v = 0.f;
    if (k < IN_RAW) {
        const float* s = (j == 0) ? Win : (j == 1) ? WB : (j == 2) ? WC : Wd;
        v = s[h * IN_RAW + k];
    }
    g_W0[idx] = __float2bfloat16(v);
}

__global__ void prep_w1_kernel(const float* __restrict__ Win, const float* __restrict__ WB,
                               const float* __restrict__ WC, const float* __restrict__ Wd) {
    int idx = blockIdx.x * 256 + threadIdx.x;          // NOUT*HID
    int r = idx / HID, k = idx % HID;
    int h = r >> 2, j = r & 3;
    const float* s = (j == 0) ? Win : (j == 1) ? WB : (j == 2) ? WC : Wd;
    g_W1[idx] = __float2bfloat16(s[h * HID + k]);
}

__global__ void prep_a_kernel(const float* __restrict__ A0, const float* __restrict__ A1) {
    int h = threadIdx.x;
    g_negA[h] = -expf(A0[h]);
    g_negA[HID + h] = -expf(A1[h]);
}

__global__ void build_x_kernel(const float* __restrict__ obs, const int* __restrict__ act,
                               const float* __restrict__ emb) {
    int t  = blockIdx.x * 8 + threadIdx.y;
    int k4 = threadIdx.x;                              // 0..23
    float4 v = make_float4(0.f, 0.f, 0.f, 0.f);
    if (k4 < 16) {
        v = *(const float4*)&obs[(size_t)t * 64 + k4 * 4];
    } else if (k4 < 18) {
        int a = act[t];
        v = *(const float4*)&emb[a * 8 + (k4 - 16) * 4];
    }
    __nv_bfloat162 h0 = __float22bfloat162_rn(make_float2(v.x, v.y));
    __nv_bfloat162 h1 = __float22bfloat162_rn(make_float2(v.z, v.w));
    uint2 o = make_uint2(*(uint32_t*)&h0, *(uint32_t*)&h1);
    *(uint2*)&g_A0[(size_t)t * K0PAD + k4 * 4] = o;
}

// ======================= shared epilogue =======================
__device__ __forceinline__ void gate_epilogue(char* smem, float acc[2][8][4],
                                              int tid, int lane, int wm, int wn,
                                              int m0, int bx_, int layer) {
    float* stage = (float*)smem;
#pragma unroll
    for (int mt = 0; mt < 2; mt++)
#pragma unroll
        for (int nt = 0; nt < 8; nt++) {
            int row = wm * 32 + mt * 16 + (lane >> 2);
            int col = wn * 64 + nt * 8 + (lane & 3) * 2;
            stage[row * 132 + col]           = acc[mt][nt][0];
            stage[row * 132 + col + 1]       = acc[mt][nt][1];
            stage[(row + 8) * 132 + col]     = acc[mt][nt][2];
            stage[(row + 8) * 132 + col + 1] = acc[mt][nt][3];
        }
    __syncthreads();

    const int chl = tid & 31;
    const int rb = tid >> 5;
    const int chg = bx_ * 32 + chl;
    const float na = g_negA[layer * HID + chg];
#pragma unroll
    for (int i = 0; i < 16; i++) {
        int row = rb + i * 8;
        float4 v = *(const float4*)&stage[row * 132 + chl * 4];  // xs, B, C, d
        float delta = 1.f / (1.f + expf(-v.w));
        float a  = expf(delta * na);
        float bx = v.y * v.x;
        size_t o = (size_t)(m0 + row) * HID + chg;
        g_ab[o] = __floats2bfloat162_rn(a, bx);
        g_c[o]  = __float2bfloat16(v.z);
    }
}

// ======================= layer-0 GEMM: single-shot K=96 =======================
// stride 208B (mod-128 offsets all distinct); A 26624B | W 26624B; 2 syncs total.
#define SMEM0_BYTES 67584

__global__ void __launch_bounds__(256, 2) gemm0_kernel() {
    extern __shared__ __align__(16) char smem[];
    const uint32_t sb = smem_u32(smem);
    const int tid = threadIdx.x, lane = tid & 31;
    const int wm = (tid >> 5) >> 1, wn = (tid >> 5) & 1;
    const int m0 = blockIdx.y * 128, n0 = blockIdx.x * 128;
    const int q = lane >> 3, r = lane & 7;

    // load A (128x96) and W (128x96), 12 x 16B per row
#pragma unroll
    for (int i = 0; i < 6; i++) {
        int idx = tid + i * 256;            // 0..1535
        int row = idx / 12, seg = idx % 12;
        CP16(sb + row * 208 + seg * 16,
             g_A0 + (size_t)(m0 + row) * K0PAD + seg * 8);
        CP16(sb + 26624 + row * 208 + seg * 16,
             g_W0 + (size_t)(n0 + row) * K0PAD + seg * 8);
    }
    CP_COMMIT();

    const uint32_t aoff = (uint32_t)(wm * 32 + (q & 1) * 8 + r) * 208 + (q >> 1) * 16;
    const uint32_t woff = 26624u + (uint32_t)(wn * 64 + (q >> 1) * 8 + r) * 208 + (q & 1) * 16;

    float acc[2][8][4];
#pragma unroll
    for (int mt = 0; mt < 2; mt++)
#pragma unroll
        for (int nt = 0; nt < 8; nt++)
#pragma unroll
            for (int i = 0; i < 4; i++) acc[mt][nt][i] = 0.f;

    CP_WAIT(0);
    __syncthreads();

#pragma unroll
    for (int ks = 0; ks < 6; ks++) {
        uint32_t ah[2][4];
#pragma unroll
        for (int mt = 0; mt < 2; mt++)
            LDSM4(ah[mt], sb + aoff + (uint32_t)mt * (16 * 208) + ks * 32);
#pragma unroll
        for (int p = 0; p < 4; p++) {
            uint32_t wh[4];
            LDSM4(wh, sb + woff + (uint32_t)p * (16 * 208) + ks * 32);
            const int nt0 = p * 2, nt1 = p * 2 + 1;
            MMA(acc[0][nt0], ah[0], (wh + 0)); MMA(acc[0][nt1], ah[0], (wh + 2));
            MMA(acc[1][nt0], ah[1], (wh + 0)); MMA(acc[1][nt1], ah[1], (wh + 2));
        }
    }
    __syncthreads();

    gate_epilogue(smem, acc, tid, lane, wm, wn, m0, blockIdx.x, 0);
}

// ======================= layer-1 GEMM: BK=64, 2-stage, 1 sync/chunk ===========
// stride 144B; stage = A 18432 | W 18432 = 36864; 2 stages = 73728.
#define STAGE1_BYTES 36864
#define SMEM1_BYTES  73728

__device__ __forceinline__ void copy_tile64(uint32_t sm, const __nv_bfloat16* g,
                                            int row0, int k0, int tid) {
#pragma unroll
    for (int i = 0; i < 4; i++) {
        int idx = tid + i * 256;            // 0..1023
        int row = idx >> 3, seg = idx & 7;
        CP16(sm + row * 144 + seg * 16,
             g + (size_t)(row0 + row) * HID + k0 + seg * 8);
    }
}

__global__ void __launch_bounds__(256, 2) gemm1_kernel() {
    extern __shared__ __align__(16) char smem[];
    const uint32_t sb = smem_u32(smem);
    const int tid = threadIdx.x, lane = tid & 31;
    const int wm = (tid >> 5) >> 1, wn = (tid >> 5) & 1;
    const int m0 = blockIdx.y * 128, n0 = blockIdx.x * 128;
    const int q = lane >> 3, r = lane & 7;

    const uint32_t aoff = (uint32_t)(wm * 32 + (q & 1) * 8 + r) * 144 + (q >> 1) * 16;
    const uint32_t woff = 18432u + (uint32_t)(wn * 64 + (q >> 1) * 8 + r) * 144 + (q & 1) * 16;

    float acc[2][8][4];
#pragma unroll
    for (int mt = 0; mt < 2; mt++)
#pragma unroll
        for (int nt = 0; nt < 8; nt++)
#pragma unroll
            for (int i = 0; i < 4; i++) acc[mt][nt][i] = 0.f;

    // prologue: chunk 0 -> buf 0
    copy_tile64(sb,         g_A1, m0, 0, tid);
    copy_tile64(sb + 18432, g_W1, n0, 0, tid);
    CP_COMMIT();

#pragma unroll
    for (int ck = 0; ck < 4; ck++) {
        CP_WAIT(0);
        __syncthreads();   // chunk ck ready; all warps done reading buf[(ck-1)&1]
        if (ck + 1 < 4) {
            uint32_t nb = sb + ((ck + 1) & 1) * STAGE1_BYTES;
            copy_tile64(nb,         g_A1, m0, (ck + 1) * 64, tid);
            copy_tile64(nb + 18432, g_W1, n0, (ck + 1) * 64, tid);
            CP_COMMIT();
        }

        const uint32_t base = sb + (ck & 1) * STAGE1_BYTES;
#pragma unroll
        for (int ks = 0; ks < 4; ks++) {
            uint32_t ah[2][4];
#pragma unroll
            for (int mt = 0; mt < 2; mt++)
                LDSM4(ah[mt], base + aoff + (uint32_t)mt * (16 * 144) + ks * 32);
#pragma unroll
            for (int p = 0; p < 4; p++) {
                uint32_t wh[4];
                LDSM4(wh, base + woff + (uint32_t)p * (16 * 144) + ks * 32);
                const int nt0 = p * 2, nt1 = p * 2 + 1;
                MMA(acc[0][nt0], ah[0], (wh + 0)); MMA(acc[0][nt1], ah[0], (wh + 2));
                MMA(acc[1][nt0], ah[1], (wh + 0)); MMA(acc[1][nt1], ah[1], (wh + 2));
            }
        }
    }
    __syncthreads();

    gate_epilogue(smem, acc, tid, lane, wm, wn, m0, blockIdx.x, 1);
}

// ======================= chunked scan =======================
__global__ void scan_pass1_kernel() {
    int h = threadIdx.x, b = blockIdx.x;
    size_t base = (size_t)b * 128 * HID + h;
    float p = 1.f, s = 0.f;
#pragma unroll 8
    for (int i = 0; i < 128; i++) {
        float2 f = __bfloat1622float2(g_ab[base + (size_t)i * HID]);
        p *= f.x;
        s = fmaf(f.x, s, f.y);
    }
    g_Ph[b * HID + h] = p;
    g_Sh[b * HID + h] = s;
}

__global__ void scan_pass2a_kernel() {
    int h = threadIdx.x, g = blockIdx.x;
    float lp = 1.f, ls = 0.f;
#pragma unroll 4
    for (int j = 0; j < 32; j++) {
        int c = g * 32 + j;
        g_Lp[c * HID + h] = lp;
        g_Ls[c * HID + h] = ls;
        float p = g_Ph[c * HID + h], s = g_Sh[c * HID + h];
        ls = fmaf(p, ls, s);
        lp *= p;
    }
    g_GP[g * HID + h] = lp;
    g_GS[g * HID + h] = ls;
}

__global__ void scan_pass2b_kernel() {
    int h = threadIdx.x;
    float acc = 0.f;
#pragma unroll
    for (int g = 0; g < NGRP; g++) {
        g_G0[g * HID + h] = acc;
        acc = fmaf(g_GP[g * HID + h], acc, g_GS[g * HID + h]);
    }
}

__global__ void scan_pass3_l0_kernel() {
    int h = threadIdx.x, b = blockIdx.x;
    size_t base = (size_t)b * 128 * HID + h;
    float hs = fmaf(g_Lp[b * HID + h], g_G0[(b >> 5) * HID + h], g_Ls[b * HID + h]);
#pragma unroll 8
    for (int i = 0; i < 128; i++) {
        size_t o = base + (size_t)i * HID;
        float2 f = __bfloat1622float2(g_ab[o]);
        hs = fmaf(f.x, hs, f.y);
        g_A1[o] = __float2bfloat16(__bfloat162float(g_c[o]) * hs);
    }
}

__global__ void __launch_bounds__(256) scan_pass3_l1_head_kernel(
        const float* __restrict__ Wout, const float* __restrict__ bout,
        float* __restrict__ out) {
    __shared__ float ws[4 * HID];
    __shared__ float bs4[4];
    __shared__ float yt[32][260];
    int tid = threadIdx.x, lane = tid & 31, w = tid >> 5;
    for (int i = tid; i < 4 * HID; i += 256) ws[i] = Wout[i];
    if (tid < 4) bs4[tid] = bout[tid];

    int h = tid, b = blockIdx.x;
    size_t base = (size_t)b * 128 * HID + h;
    float hs = fmaf(g_Lp[b * HID + h], g_G0[(b >> 5) * HID + h], g_Ls[b * HID + h]);
    __syncthreads();

    for (int sub = 0; sub < 4; sub++) {
#pragma unroll 8
        for (int j = 0; j < 32; j++) {
            size_t o = base + (size_t)(sub * 32 + j) * HID;
            float2 f = __bfloat1622float2(g_ab[o]);
            hs = fmaf(f.x, hs, f.y);
            yt[j][h] = __bfloat162float(g_c[o]) * hs;
        }
        __syncthreads();
#pragma unroll
        for (int tt = 0; tt < 4; tt++) {
            int tl = w * 4 + tt;
            float a0 = 0.f, a1 = 0.f, a2 = 0.f, a3 = 0.f;
#pragma unroll
            for (int k = 0; k < 8; k++) {
                float v = yt[tl][k * 32 + lane];
                a0 = fmaf(v, ws[0 * HID + k * 32 + lane], a0);
                a1 = fmaf(v, ws[1 * HID + k * 32 + lane], a1);
                a2 = fmaf(v, ws[2 * HID + k * 32 + lane], a2);
                a3 = fmaf(v, ws[3 * HID + k * 32 + lane], a3);
            }
#pragma unroll
            for (int o2 = 16; o2 > 0; o2 >>= 1) {
                a0 += __shfl_down_sync(0xFFFFFFFFu, a0, o2);
                a1 += __shfl_down_sync(0xFFFFFFFFu, a1, o2);
                a2 += __shfl_down_sync(0xFFFFFFFFu, a2, o2);
                a3 += __shfl_down_sync(0xFFFFFFFFu, a3, o2);
            }
            if (lane == 0) {
                float z[4] = {a0 + bs4[0], a1 + bs4[1], a2 + bs4[2], a3 + bs4[3]};
                size_t t = (size_t)b * 128 + sub * 32 + tl;
#pragma unroll
                for (int o3 = 0; o3 < 4; o3++) {
                    float zz = z[o3];
                    float sp = (zz > 20.f) ? zz : log1pf(expf(zz));
                    out[t * 4 + o3] = sp + 1.f;
                }
            }
        }
        __syncthreads();
    }
}

// ======================= launch =======================
extern "C" void kernel_launch(void* const* d_in, const int* in_sizes, int n_in,
                              void* d_out, int out_size) {
    const float* obs   = (const float*)d_in[0];
    const int*   act   = (const int*)  d_in[1];
    const float* emb   = (const float*)d_in[2];
    const float* Win0  = (const float*)d_in[3];
    const float* WB0   = (const float*)d_in[4];
    const float* WC0   = (const float*)d_in[5];
    const float* Wd0   = (const float*)d_in[6];
    const float* Alog0 = (const float*)d_in[7];
    const float* Win1  = (const float*)d_in[8];
    const float* WB1   = (const float*)d_in[9];
    const float* WC1   = (const float*)d_in[10];
    const float* Wd1   = (const float*)d_in[11];
    const float* Alog1 = (const float*)d_in[12];
    const float* Wout  = (const float*)d_in[13];
    const float* bout  = (const float*)d_in[14];
    float* out = (float*)d_out;

    cudaFuncSetAttribute(gemm0_kernel, cudaFuncAttributeMaxDynamicSharedMemorySize, SMEM0_BYTES);
    cudaFuncSetAttribute(gemm1_kernel, cudaFuncAttributeMaxDynamicSharedMemorySize, SMEM1_BYTES);

    prep_w0_kernel<<<(NOUT * K0PAD) / 256, 256>>>(Win0, WB0, WC0, Wd0);
    prep_w1_kernel<<<(NOUT * HID) / 256, 256>>>(Win1, WB1, WC1, Wd1);
    prep_a_kernel<<<1, 256>>>(Alog0, Alog1);
    build_x_kernel<<<T_LEN / 8, dim3(24, 8)>>>(obs, act, emb);

    dim3 ggrid(NOUT / 128, T_LEN / 128);   // (8, 512)

    gemm0_kernel<<<ggrid, 256, SMEM0_BYTES>>>();
    scan_pass1_kernel<<<NH, HID>>>();
    scan_pass2a_kernel<<<NGRP, HID>>>();
    scan_pass2b_kernel<<<1, HID>>>();
    scan_pass3_l0_kernel<<<NH, HID>>>();

    gemm1_kernel<<<ggrid, 256, SMEM1_BYTES>>>();
    scan_pass1_kernel<<<NH, HID>>>();
    scan_pass2a_kernel<<<NGRP, HID>>>();
    scan_pass2b_kernel<<<1, HID>>>();
    scan_pass3_l1_head_kernel<<<NH, HID>>>(Wout, bout, out);
}

// round 11
// speedup vs baseline: 2.0349x; 1.0358x over previous
#include <cuda_runtime.h>
#include <cuda_bf16.h>
#include <math.h>
#include <stdint.h>

#define T_LEN   65536
#define HID     256
#define K0PAD   96          // layer-0 K (real 72) padded
#define IN_RAW  72
#define NOUT    1024        // 4*HID interleaved weight rows
#define NH      (T_LEN / 128)   // 512 half-chunks of 128 timesteps

// ======================= scratch =======================
static __device__ __nv_bfloat16  g_A0[(size_t)T_LEN * K0PAD];
static __device__ __nv_bfloat16  g_A1[(size_t)T_LEN * HID];
static __device__ __nv_bfloat16  g_W0[NOUT * K0PAD];
static __device__ __nv_bfloat16  g_W1[NOUT * HID];
static __device__ __nv_bfloat162 g_ab[(size_t)T_LEN * HID];   // (abar, bx) packed
static __device__ __nv_bfloat16  g_c [(size_t)T_LEN * HID];
static __device__ float g_Ph [NH * HID];
static __device__ float g_Sh [NH * HID];
static __device__ float g_Hin[NH * HID];
static __device__ int   g_flag0[NH];
static __device__ int   g_flag1[NH];
static __device__ float g_negA[2 * HID];

__device__ __forceinline__ uint32_t smem_u32(const void* p) {
    uint32_t a;
    asm("{ .reg .u64 t; cvta.to.shared.u64 t, %1; cvt.u32.u64 %0, t; }" : "=r"(a) : "l"(p));
    return a;
}

#define CP16(so, gp) \
    asm volatile("cp.async.cg.shared.global [%0], [%1], 16;" :: "r"(so), "l"(gp) : "memory")
#define CP_COMMIT() asm volatile("cp.async.commit_group;" ::: "memory")
#define CP_WAIT(n)  asm volatile("cp.async.wait_group %0;" :: "n"(n) : "memory")

#define LDSM4(r, addr) \
    asm volatile("ldmatrix.sync.aligned.m8n8.x4.shared.b16 {%0,%1,%2,%3}, [%4];" \
        : "=r"((r)[0]), "=r"((r)[1]), "=r"((r)[2]), "=r"((r)[3]) : "r"(addr))

// non-volatile: lets ptxas schedule/interleave MMAs
#define MMA(d, a, b) \
    asm("mma.sync.aligned.m16n8k16.row.col.f32.bf16.bf16.f32 " \
        "{%0,%1,%2,%3}, {%4,%5,%6,%7}, {%8,%9}, {%0,%1,%2,%3};" \
        : "+f"((d)[0]), "+f"((d)[1]), "+f"((d)[2]), "+f"((d)[3]) \
        : "r"((a)[0]), "r"((a)[1]), "r"((a)[2]), "r"((a)[3]), \
          "r"((b)[0]), "r"((b)[1]))

// ======================= prep =======================
__global__ void prep_w_kernel(const float* __restrict__ Win0, const float* __restrict__ WB0,
                              const float* __restrict__ WC0, const float* __restrict__ Wd0,
                              const float* __restrict__ Win1, const float* __restrict__ WB1,
                              const float* __restrict__ WC1, const float* __restrict__ Wd1) {
    int idx = blockIdx.x * 256 + threadIdx.x;
    if (idx < NOUT * K0PAD) {
        int r = idx / K0PAD, k = idx % K0PAD;
        int h = r >> 2, j = r & 3;
        float v = 0.f;
        if (k < IN_RAW) {
            const float* s = (j == 0) ? Win0 : (j == 1) ? WB0 : (j == 2) ? WC0 : Wd0;
            v = s[h * IN_RAW + k];
        }
        g_W0[idx] = __float2bfloat16(v);
    } else {
        int i2 = idx - NOUT * K0PAD;       // < NOUT*HID
        int r = i2 / HID, k = i2 % HID;
        int h = r >> 2, j = r & 3;
        const float* s = (j == 0) ? Win1 : (j == 1) ? WB1 : (j == 2) ? WC1 : Wd1;
        g_W1[i2] = __float2bfloat16(s[h * HID + k]);
    }
}

__global__ void prep_a_kernel(const float* __restrict__ A0, const float* __restrict__ A1) {
    int h = threadIdx.x;
    g_negA[h] = -expf(A0[h]);
    g_negA[HID + h] = -expf(A1[h]);
    g_flag0[h] = 0;
    g_flag0[h + 256] = 0;
}

__global__ void build_x_kernel(const float* __restrict__ obs, const int* __restrict__ act,
                               const float* __restrict__ emb) {
    int t  = blockIdx.x * 8 + threadIdx.y;
    int k4 = threadIdx.x;                              // 0..23
    float4 v = make_float4(0.f, 0.f, 0.f, 0.f);
    if (k4 < 16) {
        v = *(const float4*)&obs[(size_t)t * 64 + k4 * 4];
    } else if (k4 < 18) {
        int a = act[t];
        v = *(const float4*)&emb[a * 8 + (k4 - 16) * 4];
    }
    __nv_bfloat162 h0 = __float22bfloat162_rn(make_float2(v.x, v.y));
    __nv_bfloat162 h1 = __float22bfloat162_rn(make_float2(v.z, v.w));
    uint2 o = make_uint2(*(uint32_t*)&h0, *(uint32_t*)&h1);
    *(uint2*)&g_A0[(size_t)t * K0PAD + k4 * 4] = o;
}

// ======================= shared GEMM epilogue =======================
__device__ __forceinline__ void gate_epilogue(char* smem, float acc[2][8][4],
                                              int tid, int lane, int wm, int wn,
                                              int m0, int bx_, int layer) {
    float* stage = (float*)smem;
#pragma unroll
    for (int mt = 0; mt < 2; mt++)
#pragma unroll
        for (int nt = 0; nt < 8; nt++) {
            int row = wm * 32 + mt * 16 + (lane >> 2);
            int col = wn * 64 + nt * 8 + (lane & 3) * 2;
            stage[row * 132 + col]           = acc[mt][nt][0];
            stage[row * 132 + col + 1]       = acc[mt][nt][1];
            stage[(row + 8) * 132 + col]     = acc[mt][nt][2];
            stage[(row + 8) * 132 + col + 1] = acc[mt][nt][3];
        }
    __syncthreads();

    const int chl = tid & 31;
    const int rb = tid >> 5;
    const int chg = bx_ * 32 + chl;
    const float na = g_negA[layer * HID + chg];
#pragma unroll
    for (int i = 0; i < 16; i++) {
        int row = rb + i * 8;
        float4 v = *(const float4*)&stage[row * 132 + chl * 4];  // xs, B, C, d
        float delta = 1.f / (1.f + expf(-v.w));
        float a  = expf(delta * na);
        float bx = v.y * v.x;
        size_t o = (size_t)(m0 + row) * HID + chg;
        g_ab[o] = __floats2bfloat162_rn(a, bx);
        g_c[o]  = __float2bfloat16(v.z);
    }
}

// ======================= layer-0 GEMM: single-shot K=96 =======================
#define SMEM0_BYTES 67584

__global__ void __launch_bounds__(256, 2) gemm0_kernel() {
    extern __shared__ __align__(16) char smem[];
    const uint32_t sb = smem_u32(smem);
    const int tid = threadIdx.x, lane = tid & 31;
    const int wm = (tid >> 5) >> 1, wn = (tid >> 5) & 1;
    const int m0 = blockIdx.y * 128, n0 = blockIdx.x * 128;
    const int q = lane >> 3, r = lane & 7;

#pragma unroll
    for (int i = 0; i < 6; i++) {
        int idx = tid + i * 256;            // 0..1535
        int row = idx / 12, seg = idx % 12;
        CP16(sb + row * 208 + seg * 16,
             g_A0 + (size_t)(m0 + row) * K0PAD + seg * 8);
        CP16(sb + 26624 + row * 208 + seg * 16,
             g_W0 + (size_t)(n0 + row) * K0PAD + seg * 8);
    }
    CP_COMMIT();

    const uint32_t aoff = (uint32_t)(wm * 32 + (q & 1) * 8 + r) * 208 + (q >> 1) * 16;
    const uint32_t woff = 26624u + (uint32_t)(wn * 64 + (q >> 1) * 8 + r) * 208 + (q & 1) * 16;

    float acc[2][8][4];
#pragma unroll
    for (int mt = 0; mt < 2; mt++)
#pragma unroll
        for (int nt = 0; nt < 8; nt++)
#pragma unroll
            for (int i = 0; i < 4; i++) acc[mt][nt][i] = 0.f;

    CP_WAIT(0);
    __syncthreads();

#pragma unroll
    for (int ks = 0; ks < 6; ks++) {
        uint32_t ah[2][4];
#pragma unroll
        for (int mt = 0; mt < 2; mt++)
            LDSM4(ah[mt], sb + aoff + (uint32_t)mt * (16 * 208) + ks * 32);
#pragma unroll
        for (int p = 0; p < 4; p++) {
            uint32_t wh[4];
            LDSM4(wh, sb + woff + (uint32_t)p * (16 * 208) + ks * 32);
            const int nt0 = p * 2, nt1 = p * 2 + 1;
            MMA(acc[0][nt0], ah[0], (wh + 0)); MMA(acc[0][nt1], ah[0], (wh + 2));
            MMA(acc[1][nt0], ah[1], (wh + 0)); MMA(acc[1][nt1], ah[1], (wh + 2));
        }
    }
    __syncthreads();

    gate_epilogue(smem, acc, tid, lane, wm, wn, m0, blockIdx.x, 0);
}

// ======================= layer-1 GEMM: BK=64, 2-stage =======================
#define STAGE1_BYTES 36864
#define SMEM1_BYTES  73728

__device__ __forceinline__ void copy_tile64(uint32_t sm, const __nv_bfloat16* g,
                                            int row0, int k0, int tid) {
#pragma unroll
    for (int i = 0; i < 4; i++) {
        int idx = tid + i * 256;            // 0..1023
        int row = idx >> 3, seg = idx & 7;
        CP16(sm + row * 144 + seg * 16,
             g + (size_t)(row0 + row) * HID + k0 + seg * 8);
    }
}

__global__ void __launch_bounds__(256, 2) gemm1_kernel() {
    extern __shared__ __align__(16) char smem[];
    const uint32_t sb = smem_u32(smem);
    const int tid = threadIdx.x, lane = tid & 31;
    const int wm = (tid >> 5) >> 1, wn = (tid >> 5) & 1;
    const int m0 = blockIdx.y * 128, n0 = blockIdx.x * 128;
    const int q = lane >> 3, r = lane & 7;

    const uint32_t aoff = (uint32_t)(wm * 32 + (q & 1) * 8 + r) * 144 + (q >> 1) * 16;
    const uint32_t woff = 18432u + (uint32_t)(wn * 64 + (q >> 1) * 8 + r) * 144 + (q & 1) * 16;

    float acc[2][8][4];
#pragma unroll
    for (int mt = 0; mt < 2; mt++)
#pragma unroll
        for (int nt = 0; nt < 8; nt++)
#pragma unroll
            for (int i = 0; i < 4; i++) acc[mt][nt][i] = 0.f;

    copy_tile64(sb,         g_A1, m0, 0, tid);
    copy_tile64(sb + 18432, g_W1, n0, 0, tid);
    CP_COMMIT();

#pragma unroll
    for (int ck = 0; ck < 4; ck++) {
        CP_WAIT(0);
        __syncthreads();
        if (ck + 1 < 4) {
            uint32_t nb = sb + ((ck + 1) & 1) * STAGE1_BYTES;
            copy_tile64(nb,         g_A1, m0, (ck + 1) * 64, tid);
            copy_tile64(nb + 18432, g_W1, n0, (ck + 1) * 64, tid);
            CP_COMMIT();
        }

        const uint32_t base = sb + (ck & 1) * STAGE1_BYTES;
#pragma unroll
        for (int ks = 0; ks < 4; ks++) {
            uint32_t ah[2][4];
#pragma unroll
            for (int mt = 0; mt < 2; mt++)
                LDSM4(ah[mt], base + aoff + (uint32_t)mt * (16 * 144) + ks * 32);
#pragma unroll
            for (int p = 0; p < 4; p++) {
                uint32_t wh[4];
                LDSM4(wh, base + woff + (uint32_t)p * (16 * 144) + ks * 32);
                const int nt0 = p * 2, nt1 = p * 2 + 1;
                MMA(acc[0][nt0], ah[0], (wh + 0)); MMA(acc[0][nt1], ah[0], (wh + 2));
                MMA(acc[1][nt0], ah[1], (wh + 0)); MMA(acc[1][nt1], ah[1], (wh + 2));
            }
        }
    }
    __syncthreads();

    gate_epilogue(smem, acc, tid, lane, wm, wn, m0, blockIdx.x, 1);
}

// ======================= fused decoupled-lookback scan =======================
// Returns h0 (state at block start). Publishes aggregate (flag=1) then
// inclusive prefix (flag=2). 8-wide lookback window.
__device__ __forceinline__ float lookback_h0(int b, int h, float p, float s,
                                             float* Ph, float* Sh, float* Hin,
                                             int* flag) {
    __shared__ int smf[8];
    float h0 = 0.f;
    if (b > 0) {
        Ph[b * HID + h] = p;
        Sh[b * HID + h] = s;
        __syncthreads();
        __threadfence();
        if (h == 0) atomicExch(&flag[b], 1);

        float Pacc = 1.f, Sacc = 0.f;
        int j = b - 1;
        for (;;) {
            int w = (j + 1 < 8) ? (j + 1) : 8;
            if (h < w) {
                int f;
                do { f = atomicAdd(&flag[j - h], 0); } while (f == 0);
                smf[h] = f;
            }
            __syncthreads();
            int d2 = w;                     // nearest predecessor with inclusive
            for (int d = 0; d < w; d++) if (smf[d] == 2) { d2 = d; break; }
            int nagg = (d2 < w) ? d2 : w;
            for (int d = 0; d < nagg; d++) {
                float P = __ldcg(&Ph[(size_t)(j - d) * HID + h]);
                float S = __ldcg(&Sh[(size_t)(j - d) * HID + h]);
                Sacc = fmaf(Pacc, S, Sacc);
                Pacc *= P;
            }
            if (d2 < w) {
                float H = __ldcg(&Hin[(size_t)(j - d2) * HID + h]);
                h0 = fmaf(Pacc, H, Sacc);
                break;
            }
            j -= w;
            if (j < 0) { h0 = Sacc; break; }
            __syncthreads();                // before smf reuse
        }
    }
    Hin[b * HID + h] = fmaf(p, h0, s);
    __syncthreads();
    __threadfence();
    if (h == 0) atomicExch(&flag[b], 2);
    return h0;
}

// layer-0 scan: local reduce -> lookback -> replay, emit bf16 A1
__global__ void __launch_bounds__(256) scan_l0_kernel() {
    int h = threadIdx.x, b = blockIdx.x;
    if (h == 0) atomicExch(&g_flag1[b], 0);   // reset layer-1 flags for this replay
    size_t base = (size_t)b * 128 * HID + h;
    float p = 1.f, s = 0.f;
#pragma unroll 8
    for (int i = 0; i < 128; i++) {
        float2 f = __bfloat1622float2(g_ab[base + (size_t)i * HID]);
        p *= f.x;
        s = fmaf(f.x, s, f.y);
    }
    float hs = lookback_h0(b, h, p, s, g_Ph, g_Sh, g_Hin, g_flag0);
#pragma unroll 8
    for (int i = 0; i < 128; i++) {
        size_t o = base + (size_t)i * HID;
        float2 f = __bfloat1622float2(g_ab[o]);
        hs = fmaf(f.x, hs, f.y);
        g_A1[o] = __float2bfloat16(__bfloat162float(g_c[o]) * hs);
    }
}

// layer-1 scan + fused output head
__global__ void __launch_bounds__(256) scan_l1_head_kernel(
        const float* __restrict__ Wout, const float* __restrict__ bout,
        float* __restrict__ out) {
    __shared__ float ws[4 * HID];
    __shared__ float bs4[4];
    __shared__ float yt[32][260];
    int tid = threadIdx.x, lane = tid & 31, w = tid >> 5;
    for (int i = tid; i < 4 * HID; i += 256) ws[i] = Wout[i];
    if (tid < 4) bs4[tid] = bout[tid];

    int h = tid, b = blockIdx.x;
    size_t base = (size_t)b * 128 * HID + h;
    float p = 1.f, s = 0.f;
#pragma unroll 8
    for (int i = 0; i < 128; i++) {
        float2 f = __bfloat1622float2(g_ab[base + (size_t)i * HID]);
        p *= f.x;
        s = fmaf(f.x, s, f.y);
    }
    float hs = lookback_h0(b, h, p, s, g_Ph, g_Sh, g_Hin, g_flag1);
    // lookback ends with __syncthreads -> ws/bs4 visible

    for (int sub = 0; sub < 4; sub++) {
#pragma unroll 8
        for (int j = 0; j < 32; j++) {
            size_t o = base + (size_t)(sub * 32 + j) * HID;
            float2 f = __bfloat1622float2(g_ab[o]);
            hs = fmaf(f.x, hs, f.y);
            yt[j][h] = __bfloat162float(g_c[o]) * hs;
        }
        __syncthreads();
#pragma unroll
        for (int tt = 0; tt < 4; tt++) {
            int tl = w * 4 + tt;
            float a0 = 0.f, a1 = 0.f, a2 = 0.f, a3 = 0.f;
#pragma unroll
            for (int k = 0; k < 8; k++) {
                float v = yt[tl][k * 32 + lane];
                a0 = fmaf(v, ws[0 * HID + k * 32 + lane], a0);
                a1 = fmaf(v, ws[1 * HID + k * 32 + lane], a1);
                a2 = fmaf(v, ws[2 * HID + k * 32 + lane], a2);
                a3 = fmaf(v, ws[3 * HID + k * 32 + lane], a3);
            }
#pragma unroll
            for (int o2 = 16; o2 > 0; o2 >>= 1) {
                a0 += __shfl_down_sync(0xFFFFFFFFu, a0, o2);
                a1 += __shfl_down_sync(0xFFFFFFFFu, a1, o2);
                a2 += __shfl_down_sync(0xFFFFFFFFu, a2, o2);
                a3 += __shfl_down_sync(0xFFFFFFFFu, a3, o2);
            }
            if (lane == 0) {
                float z[4] = {a0 + bs4[0], a1 + bs4[1], a2 + bs4[2], a3 + bs4[3]};
                size_t t = (size_t)b * 128 + sub * 32 + tl;
#pragma unroll
                for (int o3 = 0; o3 < 4; o3++) {
                    float zz = z[o3];
                    float sp = (zz > 20.f) ? zz : log1pf(expf(zz));
                    out[t * 4 + o3] = sp + 1.f;
                }
            }
        }
        __syncthreads();
    }
}

// ======================= launch =======================
extern "C" void kernel_launch(void* const* d_in, const int* in_sizes, int n_in,
                              void* d_out, int out_size) {
    const float* obs   = (const float*)d_in[0];
    const int*   act   = (const int*)  d_in[1];
    const float* emb   = (const float*)d_in[2];
    const float* Win0  = (const float*)d_in[3];
    const float* WB0   = (const float*)d_in[4];
    const float* WC0   = (const float*)d_in[5];
    const float* Wd0   = (const float*)d_in[6];
    const float* Alog0 = (const float*)d_in[7];
    const float* Win1  = (const float*)d_in[8];
    const float* WB1   = (const float*)d_in[9];
    const float* WC1   = (const float*)d_in[10];
    const float* Wd1   = (const float*)d_in[11];
    const float* Alog1 = (const float*)d_in[12];
    const float* Wout  = (const float*)d_in[13];
    const float* bout  = (const float*)d_in[14];
    float* out = (float*)d_out;

    cudaFuncSetAttribute(gemm0_kernel, cudaFuncAttributeMaxDynamicSharedMemorySize, SMEM0_BYTES);
    cudaFuncSetAttribute(gemm1_kernel, cudaFuncAttributeMaxDynamicSharedMemorySize, SMEM1_BYTES);

    prep_w_kernel<<<(NOUT * K0PAD + NOUT * HID) / 256, 256>>>(
        Win0, WB0, WC0, Wd0, Win1, WB1, WC1, Wd1);
    prep_a_kernel<<<1, 256>>>(Alog0, Alog1);
    build_x_kernel<<<T_LEN / 8, dim3(24, 8)>>>(obs, act, emb);

    dim3 ggrid(NOUT / 128, T_LEN / 128);   // (8, 512)

    gemm0_kernel<<<ggrid, 256, SMEM0_BYTES>>>();
    scan_l0_kernel<<<NH, HID>>>();

    gemm1_kernel<<<ggrid, 256, SMEM1_BYTES>>>();
    scan_l1_head_kernel<<<NH, HID>>>(Wout, bout, out);
}